// round 8
// baseline (speedup 1.0000x reference)
#include <cuda_runtime.h>

#define BATCH 16
#define CDIM  512
#define ICDIM 256
#define NPIX  4096
#define SLEN  110

// -------- scratch (static device globals; no runtime allocation) --------
__device__ float g_yconv [(size_t)BATCH * CDIM  * NPIX];   // theta rows 0..255, g rows 256..511
__device__ float g_thetaS[(size_t)BATCH * SLEN  * ICDIM];  // pooled theta [b, s, ic]
__device__ float g_g2    [(size_t)BATCH * ICDIM * SLEN];   // pooled g     [b, ic, s]
__device__ float g_tT    [(size_t)BATCH * SLEN  * CDIM];   // tT[b,s,c] = sum_ic thetaS[s,ic] w_phi[ic,c]
__device__ float g_zc    [(size_t)BATCH * CDIM  * SLEN];   // zc[b,c,s] = sum_ic w_mask[c,ic] g2[ic,s]
__device__ float g_logits[(size_t)BATCH * SLEN  * NPIX];   // [b, s, n]; softmaxed in place

// ============================================================================
// Vectorized SGEMM: C[b] = A @ B[b] (+R[b]); A [M,K] row-major, B [K,N] row-major.
// Requires M%128==0, N%128==0, K%8==0, 16B-aligned pointers.
// 128x128 tile, BK=8, 256 threads, 8x8 per thread. (R1-proven body, 23 TF/s.)
// ============================================================================
template<bool ADD_RES>
__global__ __launch_bounds__(256) void sgemm_vec(
    const float* __restrict__ A, long sA,
    const float* __restrict__ B, long sB,
    const float* __restrict__ R, long sR,
    float* __restrict__ C, long sC,
    int M, int N, int K)
{
    const int b = blockIdx.z;
    A += (long)b * sA;
    B += (long)b * sB;
    C += (long)b * sC;
    if (ADD_RES) R += (long)b * sR;

    const int m0 = blockIdx.y * 128;
    const int n0 = blockIdx.x * 128;

    __shared__ __align__(16) float As[8][128];
    __shared__ __align__(16) float Bs[8][128];

    const int tid   = threadIdx.x;
    const int arow  = tid >> 1;          // 0..127
    const int acol4 = (tid & 1) * 4;     // 0 or 4
    const int brow  = tid >> 5;          // 0..7
    const int bcol4 = (tid & 31) * 4;    // 0..124
    const int cx4 = (tid & 15) * 4;
    const int cy4 = (tid >> 4) * 4;

    float acc[8][8];
    #pragma unroll
    for (int i = 0; i < 8; i++)
        #pragma unroll
        for (int j = 0; j < 8; j++) acc[i][j] = 0.f;

    for (int k0 = 0; k0 < K; k0 += 8) {
        float4 av = *reinterpret_cast<const float4*>(&A[(long)(m0 + arow) * K + k0 + acol4]);
        float4 bv = *reinterpret_cast<const float4*>(&B[(long)(k0 + brow) * N + n0 + bcol4]);
        As[acol4 + 0][arow] = av.x;
        As[acol4 + 1][arow] = av.y;
        As[acol4 + 2][arow] = av.z;
        As[acol4 + 3][arow] = av.w;
        *reinterpret_cast<float4*>(&Bs[brow][bcol4]) = bv;
        __syncthreads();

        #pragma unroll
        for (int k = 0; k < 8; k++) {
            float4 a0 = *reinterpret_cast<const float4*>(&As[k][cy4]);
            float4 a1 = *reinterpret_cast<const float4*>(&As[k][64 + cy4]);
            float4 b0 = *reinterpret_cast<const float4*>(&Bs[k][cx4]);
            float4 b1 = *reinterpret_cast<const float4*>(&Bs[k][64 + cx4]);
            float ra[8] = {a0.x, a0.y, a0.z, a0.w, a1.x, a1.y, a1.z, a1.w};
            float rb[8] = {b0.x, b0.y, b0.z, b0.w, b1.x, b1.y, b1.z, b1.w};
            #pragma unroll
            for (int i = 0; i < 8; i++)
                #pragma unroll
                for (int j = 0; j < 8; j++)
                    acc[i][j] = fmaf(ra[i], rb[j], acc[i][j]);
        }
        __syncthreads();
    }

    #pragma unroll
    for (int ih = 0; ih < 2; ih++) {
        #pragma unroll
        for (int i = 0; i < 4; i++) {
            long row = m0 + ih * 64 + cy4 + i;
            #pragma unroll
            for (int jh = 0; jh < 2; jh++) {
                long off = row * (long)N + n0 + jh * 64 + cx4;
                float4 v;
                v.x = acc[ih * 4 + i][jh * 4 + 0];
                v.y = acc[ih * 4 + i][jh * 4 + 1];
                v.z = acc[ih * 4 + i][jh * 4 + 2];
                v.w = acc[ih * 4 + i][jh * 4 + 3];
                if (ADD_RES) {
                    float4 r = *reinterpret_cast<const float4*>(&R[off]);
                    v.x += r.x; v.y += r.y; v.z += r.z; v.w += r.w;
                }
                *reinterpret_cast<float4*>(&C[off]) = v;
            }
        }
    }
}

// ============================================================================
// Fully guarded SGEMM (+optional residual): any M, N, K. Same tiling,
// scalar guarded loads (R1-proven structure).
// ============================================================================
template<bool ADD_RES>
__global__ __launch_bounds__(256) void sgemm_gen(
    const float* __restrict__ A, long sA,
    const float* __restrict__ B, long sB,
    const float* __restrict__ R, long sR,
    float* __restrict__ C, long sC,
    int M, int N, int K)
{
    const int b = blockIdx.z;
    A += (long)b * sA;
    B += (long)b * sB;
    C += (long)b * sC;
    if (ADD_RES) R += (long)b * sR;

    const int m0 = blockIdx.y * 128;
    const int n0 = blockIdx.x * 128;

    __shared__ __align__(16) float As[8][128];
    __shared__ __align__(16) float Bs[8][128];

    const int tid = threadIdx.x;
    const int cx4 = (tid & 15) * 4;
    const int cy4 = (tid >> 4) * 4;

    float acc[8][8];
    #pragma unroll
    for (int i = 0; i < 8; i++)
        #pragma unroll
        for (int j = 0; j < 8; j++) acc[i][j] = 0.f;

    for (int k0 = 0; k0 < K; k0 += 8) {
        #pragma unroll
        for (int l = 0; l < 4; l++) {
            int idx = tid + l * 256;
            int mrow = idx >> 3;
            int kk = idx & 7;
            float va = 0.f;
            if (m0 + mrow < M && k0 + kk < K)
                va = A[(long)(m0 + mrow) * K + k0 + kk];
            As[kk][mrow] = va;

            int bkk = idx >> 7;
            int ncol = idx & 127;
            float vb = 0.f;
            if (k0 + bkk < K && n0 + ncol < N)
                vb = B[(long)(k0 + bkk) * N + n0 + ncol];
            Bs[bkk][ncol] = vb;
        }
        __syncthreads();

        #pragma unroll
        for (int k = 0; k < 8; k++) {
            float4 a0 = *reinterpret_cast<const float4*>(&As[k][cy4]);
            float4 a1 = *reinterpret_cast<const float4*>(&As[k][64 + cy4]);
            float4 b0 = *reinterpret_cast<const float4*>(&Bs[k][cx4]);
            float4 b1 = *reinterpret_cast<const float4*>(&Bs[k][64 + cx4]);
            float ra[8] = {a0.x, a0.y, a0.z, a0.w, a1.x, a1.y, a1.z, a1.w};
            float rb[8] = {b0.x, b0.y, b0.z, b0.w, b1.x, b1.y, b1.z, b1.w};
            #pragma unroll
            for (int i = 0; i < 8; i++)
                #pragma unroll
                for (int j = 0; j < 8; j++)
                    acc[i][j] = fmaf(ra[i], rb[j], acc[i][j]);
        }
        __syncthreads();
    }

    #pragma unroll
    for (int ih = 0; ih < 2; ih++) {
        #pragma unroll
        for (int i = 0; i < 4; i++) {
            int row = m0 + ih * 64 + cy4 + i;
            if (row >= M) continue;
            #pragma unroll
            for (int jh = 0; jh < 2; jh++) {
                int col = n0 + jh * 64 + cx4;
                long off = (long)row * N + col;
                #pragma unroll
                for (int j = 0; j < 4; j++) {
                    if (col + j < N) {
                        float v = acc[ih * 4 + i][jh * 4 + j];
                        if (ADD_RES) v += R[off + j];
                        C[off + j] = v;
                    }
                }
            }
        }
    }
}

// ============================================================================
// SPP adaptive max pooling over yconv [B, 512, 64, 64].
// PyTorch bins: start=(i*64)//o, end=ceil((i+1)*64/o); pyramid {1,3,6,8}, S=110.
// Channels 0..255 -> thetaS [b, s, ic]; channels 256..511 -> g2 [b, ic, s].
// ============================================================================
__global__ void spp_pool(const float* __restrict__ yconv,
                         float* __restrict__ thetaS,
                         float* __restrict__ g2)
{
    const int s = blockIdx.x;
    const int b = blockIdx.y;
    const int c = threadIdx.x;

    int o, base;
    if (s == 0)      { o = 1; base = 0; }
    else if (s < 10) { o = 3; base = 1; }
    else if (s < 46) { o = 6; base = 10; }
    else             { o = 8; base = 46; }
    const int li = s - base;
    const int i = li / o;
    const int j = li % o;
    const int h0 = (i * 64) / o;
    const int h1 = ((i + 1) * 64 + o - 1) / o;
    const int w0 = (j * 64) / o;
    const int w1 = ((j + 1) * 64 + o - 1) / o;

    const float* src = yconv + ((long)b * CDIM + c) * NPIX;
    float m = -3.4e38f;
    for (int h = h0; h < h1; h++) {
        const float* rowp = src + h * 64;
        for (int w = w0; w < w1; w++)
            m = fmaxf(m, rowp[w]);
    }

    if (c < ICDIM)
        thetaS[((long)b * SLEN + s) * ICDIM + c] = m;
    else
        g2[((long)b * ICDIM + (c - ICDIM)) * SLEN + s] = m;
}

// ============================================================================
// Softmax over the QUERY axis (n=4096) per (b, s) row, in place.
// ============================================================================
__global__ void softmax_over_n(float* __restrict__ logits)
{
    const long row = blockIdx.x;
    float* p = logits + row * (long)NPIX;
    const int tid = threadIdx.x;
    __shared__ float red[256];

    float m = -3.4e38f;
    for (int i = tid; i < NPIX; i += 256) m = fmaxf(m, p[i]);
    red[tid] = m;
    __syncthreads();
    for (int st = 128; st > 0; st >>= 1) {
        if (tid < st) red[tid] = fmaxf(red[tid], red[tid + st]);
        __syncthreads();
    }
    m = red[0];
    __syncthreads();

    float acc = 0.f;
    for (int i = tid; i < NPIX; i += 256) {
        float e = expf(p[i] - m);
        p[i] = e;
        acc += e;
    }
    red[tid] = acc;
    __syncthreads();
    for (int st = 128; st > 0; st >>= 1) {
        if (tid < st) red[tid] += red[tid + st];
        __syncthreads();
    }
    const float inv = 1.0f / red[0];

    for (int i = tid; i < NPIX; i += 256)
        p[i] *= inv;
}

// ============================================================================
// Launcher
// ============================================================================
extern "C" void kernel_launch(void* const* d_in, const int* in_sizes, int n_in,
                              void* d_out, int out_size)
{
    const float* x       = (const float*)d_in[0];  // [16, 512, 64, 64]
    const float* y       = (const float*)d_in[1];  // [16, 512, 64, 64]
    const float* w_phi   = (const float*)d_in[2];  // [256, 512]
    const float* w_theta = (const float*)d_in[3];  // [256, 512]
    const float* w_g     = (const float*)d_in[4];  // [256, 512]
    const float* w_mask  = (const float*)d_in[5];  // [512, 256]
    float* out = (float*)d_out;

    float *yconv, *thetaS, *g2, *tT, *zc, *logits;
    cudaGetSymbolAddress((void**)&yconv,  g_yconv);
    cudaGetSymbolAddress((void**)&thetaS, g_thetaS);
    cudaGetSymbolAddress((void**)&g2,     g_g2);
    cudaGetSymbolAddress((void**)&tT,     g_tT);
    cudaGetSymbolAddress((void**)&zc,     g_zc);
    cudaGetSymbolAddress((void**)&logits, g_logits);

    const long sXY = (long)CDIM * NPIX;
    const long sLg = (long)SLEN * NPIX;

    dim3 blk(256);

    // y-convs (theta + g) -> yconv halves   (M=256, N=4096, K=512 each)
    sgemm_vec<false><<<dim3(32, 2, BATCH), blk>>>(w_theta, 0, y, sXY, nullptr, 0,
                                                  yconv, sXY, 256, NPIX, 512);
    sgemm_vec<false><<<dim3(32, 2, BATCH), blk>>>(w_g, 0, y, sXY, nullptr, 0,
                                                  yconv + (long)ICDIM * NPIX, sXY, 256, NPIX, 512);
    // SPP pooling -> thetaS [b,s,ic], g2 [b,ic,s]
    spp_pool<<<dim3(SLEN, BATCH), 512>>>(yconv, thetaS, g2);

    // tT[b] = thetaS[b] @ w_phi           (M=110, N=512, K=256)
    sgemm_gen<false><<<dim3(4, 1, BATCH), blk>>>(thetaS, (long)SLEN * ICDIM, w_phi, 0,
                                                 nullptr, 0, tT, (long)SLEN * CDIM,
                                                 SLEN, CDIM, ICDIM);
    // zc[b] = w_mask @ g2[b]              (M=512, N=110, K=256)
    sgemm_gen<false><<<dim3(1, 4, BATCH), blk>>>(w_mask, 0, g2, (long)ICDIM * SLEN,
                                                 nullptr, 0, zc, (long)CDIM * SLEN,
                                                 CDIM, SLEN, ICDIM);
    // logits[b] = tT[b] @ x[b]            (M=110, N=4096, K=512)
    sgemm_gen<false><<<dim3(32, 1, BATCH), blk>>>(tT, (long)SLEN * CDIM, x, sXY,
                                                  nullptr, 0, logits, sLg,
                                                  SLEN, NPIX, CDIM);
    // softmax over n (query axis), in place
    softmax_over_n<<<BATCH * SLEN, 256>>>(logits);

    // out[b] = zc[b] @ probs[b] + x[b]    (M=512, N=4096, K=110)
    sgemm_gen<true><<<dim3(32, 4, BATCH), blk>>>(zc, (long)CDIM * SLEN, logits, sLg,
                                                 x, sXY, out, sXY,
                                                 CDIM, NPIX, SLEN);
}

// round 11
// speedup vs baseline: 1.0529x; 1.0529x over previous
#include <cuda_runtime.h>

#define BATCH 16
#define CDIM  512
#define ICDIM 256
#define NPIX  4096
#define SLEN  110
#define SPAD  128   // SLEN padded to vec-GEMM tile; pad entries are zeroed

// -------- scratch (static device globals; no runtime allocation) --------
__device__ float g_yconv [(size_t)BATCH * CDIM  * NPIX];   // theta rows 0..255, g rows 256..511
__device__ float g_thetaS[(size_t)BATCH * SPAD  * ICDIM];  // pooled theta [b, s, ic], s>=110 zero
__device__ float g_g2    [(size_t)BATCH * ICDIM * SPAD];   // pooled g     [b, ic, s], s>=110 zero
__device__ float g_tT    [(size_t)BATCH * SPAD  * CDIM];   // tT[b,s,c]; rows >=110 zero
__device__ float g_zc    [(size_t)BATCH * CDIM  * SPAD];   // zc[b,c,s]; cols >=110 zero (exact)
__device__ float g_logits[(size_t)BATCH * SPAD  * NPIX];   // [b, s, n]; softmaxed in place

// ============================================================================
// Vectorized SGEMM: C[b] = A @ B[b] (+R[b]); A [M,K] row-major, B [K,N] row-major.
// Requires M%128==0, N%128==0, K%8==0, 16B-aligned pointers.
// 128x128 tile, BK=8, 256 threads, 8x8 per thread. (~33 TF/s measured.)
// ============================================================================
template<bool ADD_RES>
__global__ __launch_bounds__(256) void sgemm_vec(
    const float* __restrict__ A, long sA,
    const float* __restrict__ B, long sB,
    const float* __restrict__ R, long sR,
    float* __restrict__ C, long sC,
    int M, int N, int K)
{
    const int b = blockIdx.z;
    A += (long)b * sA;
    B += (long)b * sB;
    C += (long)b * sC;
    if (ADD_RES) R += (long)b * sR;

    const int m0 = blockIdx.y * 128;
    const int n0 = blockIdx.x * 128;

    __shared__ __align__(16) float As[8][128];
    __shared__ __align__(16) float Bs[8][128];

    const int tid   = threadIdx.x;
    const int arow  = tid >> 1;          // 0..127
    const int acol4 = (tid & 1) * 4;     // 0 or 4
    const int brow  = tid >> 5;          // 0..7
    const int bcol4 = (tid & 31) * 4;    // 0..124
    const int cx4 = (tid & 15) * 4;
    const int cy4 = (tid >> 4) * 4;

    float acc[8][8];
    #pragma unroll
    for (int i = 0; i < 8; i++)
        #pragma unroll
        for (int j = 0; j < 8; j++) acc[i][j] = 0.f;

    for (int k0 = 0; k0 < K; k0 += 8) {
        float4 av = *reinterpret_cast<const float4*>(&A[(long)(m0 + arow) * K + k0 + acol4]);
        float4 bv = *reinterpret_cast<const float4*>(&B[(long)(k0 + brow) * N + n0 + bcol4]);
        As[acol4 + 0][arow] = av.x;
        As[acol4 + 1][arow] = av.y;
        As[acol4 + 2][arow] = av.z;
        As[acol4 + 3][arow] = av.w;
        *reinterpret_cast<float4*>(&Bs[brow][bcol4]) = bv;
        __syncthreads();

        #pragma unroll
        for (int k = 0; k < 8; k++) {
            float4 a0 = *reinterpret_cast<const float4*>(&As[k][cy4]);
            float4 a1 = *reinterpret_cast<const float4*>(&As[k][64 + cy4]);
            float4 b0 = *reinterpret_cast<const float4*>(&Bs[k][cx4]);
            float4 b1 = *reinterpret_cast<const float4*>(&Bs[k][64 + cx4]);
            float ra[8] = {a0.x, a0.y, a0.z, a0.w, a1.x, a1.y, a1.z, a1.w};
            float rb[8] = {b0.x, b0.y, b0.z, b0.w, b1.x, b1.y, b1.z, b1.w};
            #pragma unroll
            for (int i = 0; i < 8; i++)
                #pragma unroll
                for (int j = 0; j < 8; j++)
                    acc[i][j] = fmaf(ra[i], rb[j], acc[i][j]);
        }
        __syncthreads();
    }

    #pragma unroll
    for (int ih = 0; ih < 2; ih++) {
        #pragma unroll
        for (int i = 0; i < 4; i++) {
            long row = m0 + ih * 64 + cy4 + i;
            #pragma unroll
            for (int jh = 0; jh < 2; jh++) {
                long off = row * (long)N + n0 + jh * 64 + cx4;
                float4 v;
                v.x = acc[ih * 4 + i][jh * 4 + 0];
                v.y = acc[ih * 4 + i][jh * 4 + 1];
                v.z = acc[ih * 4 + i][jh * 4 + 2];
                v.w = acc[ih * 4 + i][jh * 4 + 3];
                if (ADD_RES) {
                    float4 r = *reinterpret_cast<const float4*>(&R[off]);
                    v.x += r.x; v.y += r.y; v.z += r.z; v.w += r.w;
                }
                *reinterpret_cast<float4*>(&C[off]) = v;
            }
        }
    }
}

// ============================================================================
// SPP adaptive max pooling over yconv [B, 512, 64, 64], into PADDED outputs.
// PyTorch bins: start=(i*64)//o, end=ceil((i+1)*64/o); pyramid {1,3,6,8}, S=110.
// s in [110,128): write 0.0f (zero padding — makes all downstream GEMMs exact
// with K/M = 128, because zc's padded columns become exactly zero).
// Channels 0..255 -> thetaS [b, s, ic]; channels 256..511 -> g2 [b, ic, s].
// ============================================================================
__global__ void spp_pool(const float* __restrict__ yconv,
                         float* __restrict__ thetaS,
                         float* __restrict__ g2)
{
    const int s = blockIdx.x;   // 0..127 (SPAD)
    const int b = blockIdx.y;
    const int c = threadIdx.x;  // 0..511

    float m = 0.f;
    if (s < SLEN) {
        int o, base;
        if (s == 0)      { o = 1; base = 0; }
        else if (s < 10) { o = 3; base = 1; }
        else if (s < 46) { o = 6; base = 10; }
        else             { o = 8; base = 46; }
        const int li = s - base;
        const int i = li / o;
        const int j = li % o;
        const int h0 = (i * 64) / o;
        const int h1 = ((i + 1) * 64 + o - 1) / o;
        const int w0 = (j * 64) / o;
        const int w1 = ((j + 1) * 64 + o - 1) / o;

        const float* src = yconv + ((long)b * CDIM + c) * NPIX;
        m = -3.4e38f;
        for (int h = h0; h < h1; h++) {
            const float* rowp = src + h * 64;
            for (int w = w0; w < w1; w++)
                m = fmaxf(m, rowp[w]);
        }
    }

    if (c < ICDIM)
        thetaS[((long)b * SPAD + s) * ICDIM + c] = m;
    else
        g2[((long)b * ICDIM + (c - ICDIM)) * SPAD + s] = m;
}

// ============================================================================
// Softmax over the QUERY axis (n=4096) per (b, s) row, in place.
// Padded rows (s>=110) are all-zero -> uniform probs; harmless because the
// matching zc columns are exactly zero.
// ============================================================================
__global__ void softmax_over_n(float* __restrict__ logits)
{
    const long row = blockIdx.x;                 // b*SPAD + s
    float* p = logits + row * (long)NPIX;
    const int tid = threadIdx.x;
    __shared__ float red[256];

    float m = -3.4e38f;
    for (int i = tid; i < NPIX; i += 256) m = fmaxf(m, p[i]);
    red[tid] = m;
    __syncthreads();
    for (int st = 128; st > 0; st >>= 1) {
        if (tid < st) red[tid] = fmaxf(red[tid], red[tid + st]);
        __syncthreads();
    }
    m = red[0];
    __syncthreads();

    float acc = 0.f;
    for (int i = tid; i < NPIX; i += 256) {
        float e = expf(p[i] - m);
        p[i] = e;
        acc += e;
    }
    red[tid] = acc;
    __syncthreads();
    for (int st = 128; st > 0; st >>= 1) {
        if (tid < st) red[tid] += red[tid + st];
        __syncthreads();
    }
    const float inv = 1.0f / red[0];

    for (int i = tid; i < NPIX; i += 256)
        p[i] *= inv;
}

// ============================================================================
// Launcher — every GEMM goes through the fast vec path.
// ============================================================================
extern "C" void kernel_launch(void* const* d_in, const int* in_sizes, int n_in,
                              void* d_out, int out_size)
{
    const float* x       = (const float*)d_in[0];  // [16, 512, 64, 64]
    const float* y       = (const float*)d_in[1];  // [16, 512, 64, 64]
    const float* w_phi   = (const float*)d_in[2];  // [256, 512]
    const float* w_theta = (const float*)d_in[3];  // [256, 512]
    const float* w_g     = (const float*)d_in[4];  // [256, 512]
    const float* w_mask  = (const float*)d_in[5];  // [512, 256]
    float* out = (float*)d_out;

    float *yconv, *thetaS, *g2, *tT, *zc, *logits;
    cudaGetSymbolAddress((void**)&yconv,  g_yconv);
    cudaGetSymbolAddress((void**)&thetaS, g_thetaS);
    cudaGetSymbolAddress((void**)&g2,     g_g2);
    cudaGetSymbolAddress((void**)&tT,     g_tT);
    cudaGetSymbolAddress((void**)&zc,     g_zc);
    cudaGetSymbolAddress((void**)&logits, g_logits);

    const long sXY = (long)CDIM * NPIX;        // x, y, out, yconv per-batch
    const long sTh = (long)SPAD * ICDIM;       // thetaS
    const long sG2 = (long)ICDIM * SPAD;       // g2
    const long sTT = (long)SPAD * CDIM;        // tT
    const long sZC = (long)CDIM * SPAD;        // zc
    const long sLg = (long)SPAD * NPIX;        // logits

    dim3 blk(256);

    // y-convs (theta + g) -> yconv halves   (M=256, N=4096, K=512 each)
    sgemm_vec<false><<<dim3(32, 2, BATCH), blk>>>(w_theta, 0, y, sXY, nullptr, 0,
                                                  yconv, sXY, 256, NPIX, 512);
    sgemm_vec<false><<<dim3(32, 2, BATCH), blk>>>(w_g, 0, y, sXY, nullptr, 0,
                                                  yconv + (long)ICDIM * NPIX, sXY, 256, NPIX, 512);
    // SPP pooling (padded to SPAD) -> thetaS [b,128,256], g2 [b,256,128]
    spp_pool<<<dim3(SPAD, BATCH), 512>>>(yconv, thetaS, g2);

    // tT[b] = thetaS[b] @ w_phi           (M=128, N=512, K=256) — rows >=110 zero
    sgemm_vec<false><<<dim3(4, 1, BATCH), blk>>>(thetaS, sTh, w_phi, 0,
                                                 nullptr, 0, tT, sTT,
                                                 SPAD, CDIM, ICDIM);
    // zc[b] = w_mask @ g2[b]              (M=512, N=128, K=256) — cols >=110 zero
    sgemm_vec<false><<<dim3(1, 4, BATCH), blk>>>(w_mask, 0, g2, sG2,
                                                 nullptr, 0, zc, sZC,
                                                 CDIM, SPAD, ICDIM);
    // logits[b] = tT[b] @ x[b]            (M=128, N=4096, K=512)
    sgemm_vec<false><<<dim3(32, 1, BATCH), blk>>>(tT, sTT, x, sXY,
                                                  nullptr, 0, logits, sLg,
                                                  SPAD, NPIX, CDIM);
    // softmax over n (query axis), in place — all SPAD rows (pad rows harmless)
    softmax_over_n<<<BATCH * SPAD, 256>>>(logits);

    // out[b] = zc[b] @ probs[b] + x[b]    (M=512, N=4096, K=128)
    sgemm_vec<true><<<dim3(32, 4, BATCH), blk>>>(zc, sZC, logits, sLg,
                                                 x, sXY, out, sXY,
                                                 CDIM, NPIX, SPAD);
}

// round 15
// speedup vs baseline: 1.3169x; 1.2508x over previous
#include <cuda_runtime.h>

#define BATCH 16
#define CDIM  512
#define ICDIM 256
#define NPIX  4096
#define SLEN  110
#define SPAD  128   // SLEN padded to vec-GEMM tile; pad entries are zeroed

// -------- scratch (static device globals; no runtime allocation) --------
__device__ float g_yconv [(size_t)BATCH * CDIM  * NPIX];   // theta rows 0..255, g rows 256..511
__device__ float g_thetaS[(size_t)BATCH * SPAD  * ICDIM];  // pooled theta [b, s, ic], s>=110 zero
__device__ float g_g2    [(size_t)BATCH * ICDIM * SPAD];   // pooled g     [b, ic, s], s>=110 zero
__device__ float g_tT    [(size_t)BATCH * SPAD  * CDIM];   // tT[b,s,c]; rows >=110 zero
__device__ float g_zc    [(size_t)BATCH * CDIM  * SPAD];   // zc[b,c,s]; cols >=110 zero (exact)
__device__ float g_logits[(size_t)BATCH * SPAD  * NPIX];   // [b, s, n]; softmaxed in place

// ============================================================================
// Vectorized SGEMM: C[b] = A @ B[b] (+R[b]); A [M,K] row-major, B [K,N] row-major.
// Requires M%128==0, N%128==0, K%8==0, 16B-aligned pointers.
// 128x128 tile, BK=8, 256 threads, 8x8 per thread.
// DOUBLE-BUFFERED smem: one __syncthreads per k-step; gmem load of the next
// tile overlaps the compute of the current one. 2 CTAs/SM pinned.
// ============================================================================
template<bool ADD_RES>
__global__ __launch_bounds__(256, 2) void sgemm_vec(
    const float* __restrict__ A, long sA,
    const float* __restrict__ B, long sB,
    const float* __restrict__ R, long sR,
    float* __restrict__ C, long sC,
    int M, int N, int K)
{
    const int b = blockIdx.z;
    A += (long)b * sA;
    B += (long)b * sB;
    C += (long)b * sC;
    if (ADD_RES) R += (long)b * sR;

    const int m0 = blockIdx.y * 128;
    const int n0 = blockIdx.x * 128;

    __shared__ __align__(16) float As[2][8][128];
    __shared__ __align__(16) float Bs[2][8][128];

    const int tid   = threadIdx.x;
    const int arow  = tid >> 1;          // 0..127
    const int acol4 = (tid & 1) * 4;     // 0 or 4
    const int brow  = tid >> 5;          // 0..7
    const int bcol4 = (tid & 31) * 4;    // 0..124
    const int cx4 = (tid & 15) * 4;
    const int cy4 = (tid >> 4) * 4;

    float acc[8][8];
    #pragma unroll
    for (int i = 0; i < 8; i++)
        #pragma unroll
        for (int j = 0; j < 8; j++) acc[i][j] = 0.f;

    const float* pA = &A[(long)(m0 + arow) * K + acol4];
    const float* pB = &B[(long)brow * N + n0 + bcol4];

    // preload tile 0 into buffer 0
    float4 av = *reinterpret_cast<const float4*>(pA);
    float4 bv = *reinterpret_cast<const float4*>(pB);
    As[0][acol4 + 0][arow] = av.x;
    As[0][acol4 + 1][arow] = av.y;
    As[0][acol4 + 2][arow] = av.z;
    As[0][acol4 + 3][arow] = av.w;
    *reinterpret_cast<float4*>(&Bs[0][brow][bcol4]) = bv;
    __syncthreads();

    int cur = 0;
    for (int k0 = 0; k0 < K; k0 += 8) {
        const bool has_next = (k0 + 8 < K);
        if (has_next) {   // issue next-tile gmem loads before computing
            av = *reinterpret_cast<const float4*>(pA + k0 + 8);
            bv = *reinterpret_cast<const float4*>(pB + (long)(k0 + 8) * N);
        }

        #pragma unroll
        for (int k = 0; k < 8; k++) {
            float4 a0 = *reinterpret_cast<const float4*>(&As[cur][k][cy4]);
            float4 a1 = *reinterpret_cast<const float4*>(&As[cur][k][64 + cy4]);
            float4 b0 = *reinterpret_cast<const float4*>(&Bs[cur][k][cx4]);
            float4 b1 = *reinterpret_cast<const float4*>(&Bs[cur][k][64 + cx4]);
            float ra[8] = {a0.x, a0.y, a0.z, a0.w, a1.x, a1.y, a1.z, a1.w};
            float rb[8] = {b0.x, b0.y, b0.z, b0.w, b1.x, b1.y, b1.z, b1.w};
            #pragma unroll
            for (int i = 0; i < 8; i++)
                #pragma unroll
                for (int j = 0; j < 8; j++)
                    acc[i][j] = fmaf(ra[i], rb[j], acc[i][j]);
        }

        if (has_next) {   // write into the other buffer; single sync
            const int nxt = cur ^ 1;
            As[nxt][acol4 + 0][arow] = av.x;
            As[nxt][acol4 + 1][arow] = av.y;
            As[nxt][acol4 + 2][arow] = av.z;
            As[nxt][acol4 + 3][arow] = av.w;
            *reinterpret_cast<float4*>(&Bs[nxt][brow][bcol4]) = bv;
            __syncthreads();
            cur = nxt;
        }
    }

    #pragma unroll
    for (int ih = 0; ih < 2; ih++) {
        #pragma unroll
        for (int i = 0; i < 4; i++) {
            long row = m0 + ih * 64 + cy4 + i;
            #pragma unroll
            for (int jh = 0; jh < 2; jh++) {
                long off = row * (long)N + n0 + jh * 64 + cx4;
                float4 v;
                v.x = acc[ih * 4 + i][jh * 4 + 0];
                v.y = acc[ih * 4 + i][jh * 4 + 1];
                v.z = acc[ih * 4 + i][jh * 4 + 2];
                v.w = acc[ih * 4 + i][jh * 4 + 3];
                if (ADD_RES) {
                    float4 r = *reinterpret_cast<const float4*>(&R[off]);
                    v.x += r.x; v.y += r.y; v.z += r.z; v.w += r.w;
                }
                *reinterpret_cast<float4*>(&C[off]) = v;
            }
        }
    }
}

// ============================================================================
// SPP adaptive max pooling over yconv [B, 512, 64, 64], into PADDED outputs.
// PyTorch bins: start=(i*64)//o, end=ceil((i+1)*64/o); pyramid {1,3,6,8}, S=110.
// s in [110,128): write 0.0f (zero padding — downstream GEMMs stay exact
// because zc's padded columns become exactly zero).
// Channels 0..255 -> thetaS [b, s, ic]; channels 256..511 -> g2 [b, ic, s].
// ============================================================================
__global__ void spp_pool(const float* __restrict__ yconv,
                         float* __restrict__ thetaS,
                         float* __restrict__ g2)
{
    const int s = blockIdx.x;   // 0..127 (SPAD)
    const int b = blockIdx.y;
    const int c = threadIdx.x;  // 0..511

    float m = 0.f;
    if (s < SLEN) {
        int o, base;
        if (s == 0)      { o = 1; base = 0; }
        else if (s < 10) { o = 3; base = 1; }
        else if (s < 46) { o = 6; base = 10; }
        else             { o = 8; base = 46; }
        const int li = s - base;
        const int i = li / o;
        const int j = li % o;
        const int h0 = (i * 64) / o;
        const int h1 = ((i + 1) * 64 + o - 1) / o;
        const int w0 = (j * 64) / o;
        const int w1 = ((j + 1) * 64 + o - 1) / o;

        const float* src = yconv + ((long)b * CDIM + c) * NPIX;
        m = -3.4e38f;
        for (int h = h0; h < h1; h++) {
            const float* rowp = src + h * 64;
            for (int w = w0; w < w1; w++)
                m = fmaxf(m, rowp[w]);
        }
    }

    if (c < ICDIM)
        thetaS[((long)b * SPAD + s) * ICDIM + c] = m;
    else
        g2[((long)b * ICDIM + (c - ICDIM)) * SPAD + s] = m;
}

// ============================================================================
// Softmax over the QUERY axis (n=4096) per (b, s) row, in place.
// Padded rows (s>=110) are all-zero -> uniform probs; harmless because the
// matching zc columns are exactly zero.
// ============================================================================
__global__ void softmax_over_n(float* __restrict__ logits)
{
    const long row = blockIdx.x;                 // b*SPAD + s
    float* p = logits + row * (long)NPIX;
    const int tid = threadIdx.x;
    __shared__ float red[256];

    float m = -3.4e38f;
    for (int i = tid; i < NPIX; i += 256) m = fmaxf(m, p[i]);
    red[tid] = m;
    __syncthreads();
    for (int st = 128; st > 0; st >>= 1) {
        if (tid < st) red[tid] = fmaxf(red[tid], red[tid + st]);
        __syncthreads();
    }
    m = red[0];
    __syncthreads();

    float acc = 0.f;
    for (int i = tid; i < NPIX; i += 256) {
        float e = expf(p[i] - m);
        p[i] = e;
        acc += e;
    }
    red[tid] = acc;
    __syncthreads();
    for (int st = 128; st > 0; st >>= 1) {
        if (tid < st) red[tid] += red[tid + st];
        __syncthreads();
    }
    const float inv = 1.0f / red[0];

    for (int i = tid; i < NPIX; i += 256)
        p[i] *= inv;
}

// ============================================================================
// Launcher — every GEMM goes through the vec path (SPAD padding).
// ============================================================================
extern "C" void kernel_launch(void* const* d_in, const int* in_sizes, int n_in,
                              void* d_out, int out_size)
{
    const float* x       = (const float*)d_in[0];  // [16, 512, 64, 64]
    const float* y       = (const float*)d_in[1];  // [16, 512, 64, 64]
    const float* w_phi   = (const float*)d_in[2];  // [256, 512]
    const float* w_theta = (const float*)d_in[3];  // [256, 512]
    const float* w_g     = (const float*)d_in[4];  // [256, 512]
    const float* w_mask  = (const float*)d_in[5];  // [512, 256]
    float* out = (float*)d_out;

    float *yconv, *thetaS, *g2, *tT, *zc, *logits;
    cudaGetSymbolAddress((void**)&yconv,  g_yconv);
    cudaGetSymbolAddress((void**)&thetaS, g_thetaS);
    cudaGetSymbolAddress((void**)&g2,     g_g2);
    cudaGetSymbolAddress((void**)&tT,     g_tT);
    cudaGetSymbolAddress((void**)&zc,     g_zc);
    cudaGetSymbolAddress((void**)&logits, g_logits);

    const long sXY = (long)CDIM * NPIX;        // x, y, out, yconv per-batch
    const long sTh = (long)SPAD * ICDIM;       // thetaS
    const long sG2 = (long)ICDIM * SPAD;       // g2
    const long sTT = (long)SPAD * CDIM;        // tT
    const long sZC = (long)CDIM * SPAD;        // zc
    const long sLg = (long)SPAD * NPIX;        // logits

    dim3 blk(256);

    // y-convs (theta + g) -> yconv halves   (M=256, N=4096, K=512 each)
    sgemm_vec<false><<<dim3(32, 2, BATCH), blk>>>(w_theta, 0, y, sXY, nullptr, 0,
                                                  yconv, sXY, 256, NPIX, 512);
    sgemm_vec<false><<<dim3(32, 2, BATCH), blk>>>(w_g, 0, y, sXY, nullptr, 0,
                                                  yconv + (long)ICDIM * NPIX, sXY, 256, NPIX, 512);
    // SPP pooling (padded to SPAD) -> thetaS [b,128,256], g2 [b,256,128]
    spp_pool<<<dim3(SPAD, BATCH), 512>>>(yconv, thetaS, g2);

    // tT[b] = thetaS[b] @ w_phi           (M=128, N=512, K=256)
    sgemm_vec<false><<<dim3(4, 1, BATCH), blk>>>(thetaS, sTh, w_phi, 0,
                                                 nullptr, 0, tT, sTT,
                                                 SPAD, CDIM, ICDIM);
    // zc[b] = w_mask @ g2[b]              (M=512, N=128, K=256)
    sgemm_vec<false><<<dim3(1, 4, BATCH), blk>>>(w_mask, 0, g2, sG2,
                                                 nullptr, 0, zc, sZC,
                                                 CDIM, SPAD, ICDIM);
    // logits[b] = tT[b] @ x[b]            (M=128, N=4096, K=512)
    sgemm_vec<false><<<dim3(32, 1, BATCH), blk>>>(tT, sTT, x, sXY,
                                                  nullptr, 0, logits, sLg,
                                                  SPAD, NPIX, CDIM);
    // softmax over n (query axis), in place
    softmax_over_n<<<BATCH * SPAD, 256>>>(logits);

    // out[b] = zc[b] @ probs[b] + x[b]    (M=512, N=4096, K=128)
    sgemm_vec<true><<<dim3(32, 4, BATCH), blk>>>(zc, sZC, logits, sLg,
                                                 x, sXY, out, sXY,
                                                 CDIM, NPIX, SPAD);
}